// round 15
// baseline (speedup 1.0000x reference)
#include <cuda_runtime.h>
#include <cuda_fp16.h>
#include <stdint.h>

// ---------------- problem constants ----------------
#define B_    2048
#define V_    2
#define D_    256
#define NTOT  4096
#define NB_   32              // 128-wide blocks per dimension
#define NTILES 528            // NB*(NB+1)/2 upper-triangular tiles
#define NPREP  256            // producer CTAs for the prep phase
#define GAMMA_F   0.9f
#define TEMP_F    0.07f
#define BASET_F   0.07f

// ---------------- device scratch ----------------
__device__ __half g_Fh[NTOT * D_];
__device__ float g_Mp[NB_ * NTOT];   // per-(slot,row) raw max
__device__ float g_Ep[NB_ * NTOT];   // per-(slot,row) sum e,  e = exp((raw-1)/T)
__device__ float g_Gp[NB_ * NTOT];   // per-(slot,row) sum e*raw
__device__ float g_SP[NTOT];         // raw positive logit
__device__ float g_Lp[8];
__device__ unsigned int g_prep;
__device__ unsigned int g_ctr;
__device__ unsigned int g_fin;

// ---------------- helpers ----------------
__device__ __forceinline__ uint32_t smem_u32(const void* p) {
    uint32_t a;
    asm("{ .reg .u64 t; cvta.to.shared.u64 t, %1; cvt.u32.u64 %0, t; }" : "=r"(a) : "l"(p));
    return a;
}
__device__ __forceinline__ uint32_t sw128(uint32_t off) {
    return off ^ ((off >> 3) & 0x70);
}
__device__ __forceinline__ void ldsm_x4(uint32_t* r, uint32_t addr) {
    asm volatile("ldmatrix.sync.aligned.m8n8.x4.shared.b16 {%0,%1,%2,%3}, [%4];"
                 : "=r"(r[0]), "=r"(r[1]), "=r"(r[2]), "=r"(r[3]) : "r"(addr));
}
__device__ __forceinline__ void mma_f16(float* c, const uint32_t* a, uint32_t b0, uint32_t b1) {
    asm volatile("mma.sync.aligned.m16n8k16.row.col.f32.f16.f16.f32 "
                 "{%0,%1,%2,%3}, {%4,%5,%6,%7}, {%8,%9}, {%0,%1,%2,%3};"
                 : "+f"(c[0]), "+f"(c[1]), "+f"(c[2]), "+f"(c[3])
                 : "r"(a[0]), "r"(a[1]), "r"(a[2]), "r"(a[3]), "r"(b0), "r"(b1));
}
__device__ __forceinline__ void cp16(uint32_t saddr, const void* gptr) {
    asm volatile("cp.async.cg.shared.global [%0], [%1], 16;"
                 :: "r"(saddr), "l"(__cvta_generic_to_global(gptr)));
}
#define CP_COMMIT() asm volatile("cp.async.commit_group;" ::: "memory")
#define CP_WAIT(n)  asm volatile("cp.async.wait_group %0;" :: "n"(n) : "memory")
__device__ __forceinline__ unsigned int ld_cg_u32(const unsigned int* p) {
    unsigned int v;
    asm volatile("ld.global.cg.u32 %0, [%1];" : "=r"(v) : "l"(p));
    return v;
}

// ---------------- single fused kernel, 256 threads, 3-stage pipeline ----------------
#define OFF_A 0
#define OFF_B 16384
#define STAGE_BYTES 32768
#define NSTAGE 3
#define SMEM_BYTES  (NSTAGE * STAGE_BYTES)

__global__ void __launch_bounds__(256, 2) fused_kernel(const float* __restrict__ feats,
                                                       const int* __restrict__ index,
                                                       const float* __restrict__ u,
                                                       float* __restrict__ out) {
    extern __shared__ char smem[];
    const uint32_t sb = smem_u32(smem);
    const int tid  = threadIdx.x;
    const int lane = tid & 31;
    const int wid  = tid >> 5;
    const int wm   = wid & 1;       // M half (64 rows)
    const int wn   = wid >> 1;      // N quarter (32 cols)

    // ---------------- phase 0: prep (producer CTAs bid < 256, all wave-1) ----------------
    if (blockIdx.x < NPREP) {
#pragma unroll
        for (int it = 0; it < 4; it++) {
            int e = (blockIdx.x * 1024 + it * 256 + tid) * 4;
            int n = e >> 8;
            int d = e & 255;
            int v = n >> 11;
            int b = n & 2047;
            float4 f = *(const float4*)&feats[((b << 1) | v) * D_ + d];
            uint2 hp;
            hp.x = ((uint32_t)__half_as_ushort(__float2half(f.y)) << 16) | __half_as_ushort(__float2half(f.x));
            hp.y = ((uint32_t)__half_as_ushort(__float2half(f.w)) << 16) | __half_as_ushort(__float2half(f.z));
            *(uint2*)&g_Fh[e] = hp;
        }
        __threadfence();
        __syncthreads();
        if (tid == 0) atomicAdd(&g_prep, 1u);
    }
    if (tid == 0) {
        while (ld_cg_u32(&g_prep) < (unsigned)NPREP) { __nanosleep(60); }
    }
    __syncthreads();
    __threadfence();

    // decode upper-triangular tile (bi, bj), bi <= bj
    int bi = 0, rem = blockIdx.x;
    while (rem >= (NB_ - bi)) { rem -= (NB_ - bi); bi++; }
    const int bj = bi + rem;
    const int row0 = bi * 128;
    const int col0 = bj * 128;

    // staging coords
    int sr[4], sc[4];
    uint32_t ssw[4];
#pragma unroll
    for (int it = 0; it < 4; it++) {
        int q = tid + it * 256;
        sr[it] = q >> 3;
        sc[it] = q & 7;
        ssw[it] = sw128((uint32_t)(sr[it] * 128 + sc[it] * 16));
    }

#define PREFETCH(KC, STG)                                                                           \
    do {                                                                                            \
        _Pragma("unroll")                                                                           \
        for (int it = 0; it < 4; it++) {                                                            \
            cp16((STG) + OFF_A + ssw[it], &g_Fh[(row0 + sr[it]) * D_ + (KC) * 64 + sc[it] * 8]);    \
            cp16((STG) + OFF_B + ssw[it], &g_Fh[(col0 + sr[it]) * D_ + (KC) * 64 + sc[it] * 8]);    \
        }                                                                                           \
        CP_COMMIT();                                                                                \
    } while (0)

    // prefetch chunks 0 and 1 into stages 0 and 1
    PREFETCH(0, sb);
    PREFETCH(1, sb + STAGE_BYTES);

    float acc[4][4][4];
#pragma unroll
    for (int mi = 0; mi < 4; mi++)
#pragma unroll
        for (int nj = 0; nj < 4; nj++)
#pragma unroll
            for (int c = 0; c < 4; c++) acc[mi][nj][c] = 0.0f;

    const int arow  = wm * 64 + (lane & 7) + ((lane >> 3) & 1) * 8;
    const int akc0  = (lane >> 4) * 8;
    const int brow  = wn * 32 + (lane & 7) + (lane >> 4) * 8;
    const int bkc0  = ((lane >> 3) & 1) * 8;

    for (int kc = 0; kc < 4; kc++) {
        // wait for chunk kc's group (groups committed so far: 0..kc+1 -> allow 1 pending)
        if (kc < 3) { CP_WAIT(1); } else { CP_WAIT(0); }
        __syncthreads();   // chunk-kc data visible to all; compute(kc-1) finished by all

        // prefetch chunk kc+2 into stage (kc+2)%3 (readers of that stage finished at kc-1)
        if (kc < 2) PREFETCH(kc + 2, sb + ((kc + 2) % NSTAGE) * STAGE_BYTES);

        const uint32_t cb = sb + (kc % NSTAGE) * STAGE_BYTES;
#pragma unroll
        for (int ks = 0; ks < 4; ks++) {
            const int akc = ks * 16 + akc0;
            const int bkc = ks * 16 + bkc0;
            uint32_t a[4][4], b[2][4];
#pragma unroll
            for (int mi = 0; mi < 4; mi++)
                ldsm_x4(a[mi], cb + OFF_A + sw128((uint32_t)((arow + mi * 16) * 128 + akc * 2)));
#pragma unroll
            for (int b2 = 0; b2 < 2; b2++)
                ldsm_x4(b[b2], cb + OFF_B + sw128((uint32_t)((brow + b2 * 16) * 128 + bkc * 2)));
#pragma unroll
            for (int mi = 0; mi < 4; mi++)
#pragma unroll
                for (int nj = 0; nj < 4; nj++) {
                    uint32_t b0 = (nj & 1) ? b[nj >> 1][2] : b[nj >> 1][0];
                    uint32_t b1 = (nj & 1) ? b[nj >> 1][3] : b[nj >> 1][1];
                    mma_f16(acc[mi][nj], a[mi], b0, b1);
                }
        }
        // no trailing sync: next iteration's post-wait sync orders reuse
    }
    __syncthreads();   // protect smem reuse by the epilogue reduction arrays

    // ---------------- epilogue: fused row+col stats, fixed-m0 exp ----------------
    float* redm = (float*)smem;          // [128][4] row partials
    float* rede = redm + 512;
    float* redg = rede + 512;
    float* colm_s = redg + 512;          // [128][2] col partials
    float* cole_s = colm_s + 256;
    float* colg_s = cole_s + 256;
    const float invT = 1.0f / TEMP_F;
    const bool offd = (bi != bj);

    float colE[8], colG[8], colM[8];
#pragma unroll
    for (int k = 0; k < 8; k++) { colE[k] = 0.0f; colG[k] = 0.0f; colM[k] = -1e30f; }

#pragma unroll
    for (int mi = 0; mi < 4; mi++) {
#pragma unroll
        for (int h = 0; h < 2; h++) {
            int lr = wm * 64 + mi * 16 + h * 8 + (lane >> 2);
            int gi = row0 + lr;
            int posj = (gi + B_) & (NTOT - 1);
            float rE = 0.0f, rG = 0.0f, rM = -1e30f;
#pragma unroll
            for (int nj = 0; nj < 4; nj++) {
#pragma unroll
                for (int c = 0; c < 2; c++) {
                    const int k = nj * 2 + c;
                    float raw = acc[mi][nj][h * 2 + c];
                    int gj = col0 + wn * 32 + nj * 8 + (lane & 3) * 2 + c;
                    rM = fmaxf(rM, raw);
                    if (offd) colM[k] = fmaxf(colM[k], raw);
                    if (gj == posj) {
                        g_SP[gi] = raw;                  // row gi's positive
                        g_SP[gj] = raw;                  // row gj's positive (symmetric)
                    } else {
                        float e = __expf((raw - 1.0f) * invT);
                        rE += e;
                        rG = fmaf(e, raw, rG);
                        if (offd) {
                            colE[k] += e;
                            colG[k] = fmaf(e, raw, colG[k]);
                        }
                    }
                }
            }
            rM = fmaxf(rM, __shfl_xor_sync(0xffffffffu, rM, 1));
            rM = fmaxf(rM, __shfl_xor_sync(0xffffffffu, rM, 2));
            rE += __shfl_xor_sync(0xffffffffu, rE, 1);
            rE += __shfl_xor_sync(0xffffffffu, rE, 2);
            rG += __shfl_xor_sync(0xffffffffu, rG, 1);
            rG += __shfl_xor_sync(0xffffffffu, rG, 2);
            if ((lane & 3) == 0) {
                redm[lr * 4 + wn] = rM;
                rede[lr * 4 + wn] = rE;
                redg[lr * 4 + wn] = rG;
            }
        }
    }

    if (offd) {
#pragma unroll
        for (int k = 0; k < 8; k++) {
            int cid = wn * 32 + (k >> 1) * 8 + (lane & 3) * 2 + (k & 1);
            float m = colM[k], E = colE[k], G = colG[k];
            m = fmaxf(m, __shfl_xor_sync(0xffffffffu, m, 4));
            m = fmaxf(m, __shfl_xor_sync(0xffffffffu, m, 8));
            m = fmaxf(m, __shfl_xor_sync(0xffffffffu, m, 16));
            E += __shfl_xor_sync(0xffffffffu, E, 4);
            E += __shfl_xor_sync(0xffffffffu, E, 8);
            E += __shfl_xor_sync(0xffffffffu, E, 16);
            G += __shfl_xor_sync(0xffffffffu, G, 4);
            G += __shfl_xor_sync(0xffffffffu, G, 8);
            G += __shfl_xor_sync(0xffffffffu, G, 16);
            if ((lane >> 2) == 0) {
                colm_s[cid * 2 + wm] = m;
                cole_s[cid * 2 + wm] = E;
                colg_s[cid * 2 + wm] = G;
            }
        }
    }

    __syncthreads();
    if (tid < 128) {
        float mm = redm[tid * 4], ee = rede[tid * 4], gg = redg[tid * 4];
#pragma unroll
        for (int t = 1; t < 4; t++) {
            mm = fmaxf(mm, redm[tid * 4 + t]);
            ee += rede[tid * 4 + t];
            gg += redg[tid * 4 + t];
        }
        g_Mp[bj * NTOT + row0 + tid] = mm;
        g_Ep[bj * NTOT + row0 + tid] = ee;
        g_Gp[bj * NTOT + row0 + tid] = gg;
    } else if (offd && tid < 256) {
        int cid = tid - 128;
        float mm = fmaxf(colm_s[cid * 2], colm_s[cid * 2 + 1]);
        float ee = cole_s[cid * 2] + cole_s[cid * 2 + 1];
        float gg = colg_s[cid * 2] + colg_s[cid * 2 + 1];
        g_Mp[bi * NTOT + col0 + cid] = mm;
        g_Ep[bi * NTOT + col0 + cid] = ee;
        g_Gp[bi * NTOT + col0 + cid] = gg;
    }

    // ---------------- done-ticket + fused combine (CTAs 0..7) ----------------
    __threadfence();
    __syncthreads();
    if (tid == 0) atomicAdd(&g_ctr, 1u);

    if (blockIdx.x < 8) {
        if (tid == 0) {
            while (ld_cg_u32(&g_ctr) < (unsigned)NTILES) { __nanosleep(100); }
        }
        __syncthreads();
        __threadfence();

        __shared__ float red[8];
        int b = blockIdx.x * 256 + tid;            // [0, 2048)
        float m1 = -1e30f, E1 = 0.0f, G1 = 0.0f;   // row b
        float m2 = -1e30f, E2 = 0.0f, G2 = 0.0f;   // row b+2048
#pragma unroll
        for (int s = 0; s < NB_; s++) {
            m1 = fmaxf(m1, g_Mp[s * NTOT + b]);
            E1 += g_Ep[s * NTOT + b];
            G1 += g_Gp[s * NTOT + b];
            m2 = fmaxf(m2, g_Mp[s * NTOT + B_ + b]);
            E2 += g_Ep[s * NTOT + B_ + b];
            G2 += g_Gp[s * NTOT + B_ + b];
        }
        const float invT2 = 1.0f / TEMP_F;
        float em1 = __expf((1.0f - m1) * invT2);
        float em2 = __expf((1.0f - m2) * invT2);
        float u_new = (1.0f - GAMMA_F) * u[index[b]] + GAMMA_F * em1 * E1;
        float t1 = em1 * invT2 * (G1 - m1 * E1) / u_new;
        float t2 = em2 * invT2 * (G2 - m2 * E2) / u_new;
        const float k = -(TEMP_F / BASET_F) * (1.0f / (float)NTOT);
        float val = k * ((invT2 * (g_SP[b]      - m1) - t1) +
                         (invT2 * (g_SP[B_ + b] - m2) - t2));
#pragma unroll
        for (int o = 16; o; o >>= 1) val += __shfl_down_sync(0xffffffffu, val, o);
        if ((tid & 31) == 0) red[tid >> 5] = val;
        __syncthreads();
        if (tid < 8) {
            float v = red[tid];
#pragma unroll
            for (int o = 4; o; o >>= 1) v += __shfl_down_sync(0xffu, v, o);
            if (tid == 0) {
                g_Lp[blockIdx.x] = v;
                __threadfence();
                unsigned int t = atomicAdd(&g_fin, 1u);
                if (t == 7u) {
                    float s = 0.0f;
#pragma unroll
                    for (int i = 0; i < 8; i++) s += g_Lp[i];
                    out[0] = s;
                    g_prep = 0;
                    g_ctr  = 0;
                    g_fin  = 0;
                }
            }
        }
    }
}

// ---------------- launch ----------------
extern "C" void kernel_launch(void* const* d_in, const int* in_sizes, int n_in,
                              void* d_out, int out_size) {
    const int*   d_index = nullptr;
    const float* d_feats = nullptr;
    const float* d_u     = nullptr;
    for (int i = 0; i < n_in; i++) {
        if (in_sizes[i] == B_)                 d_index = (const int*)d_in[i];
        else if (in_sizes[i] == B_ * V_ * D_)  d_feats = (const float*)d_in[i];
        else                                   d_u     = (const float*)d_in[i];
    }
    float* out = (float*)d_out;

    cudaFuncSetAttribute(fused_kernel,
                         cudaFuncAttributeMaxDynamicSharedMemorySize, SMEM_BYTES);

    fused_kernel<<<NTILES, 256, SMEM_BYTES>>>(d_feats, d_index, d_u, out);
}

// round 16
// speedup vs baseline: 1.0163x; 1.0163x over previous
#include <cuda_runtime.h>
#include <cuda_fp16.h>
#include <stdint.h>

// ---------------- problem constants ----------------
#define B_    2048
#define V_    2
#define D_    256
#define NTOT  4096
#define NB_   32              // 128-wide blocks per dimension
#define NTILES 528            // NB*(NB+1)/2 upper-triangular tiles
#define NPREP  256            // producer CTAs for the prep phase
#define GAMMA_F   0.9f
#define TEMP_F    0.07f
#define BASET_F   0.07f

// ---------------- device scratch ----------------
__device__ __half g_Fh[NTOT * D_];
__device__ float g_Mp[NB_ * NTOT];   // per-(slot,row) raw max
__device__ float g_Ep[NB_ * NTOT];   // per-(slot,row) sum e,  e = exp((raw-1)/T)
__device__ float g_Gp[NB_ * NTOT];   // per-(slot,row) sum e*raw
__device__ float g_SP[NTOT];         // raw positive logit
__device__ float g_Lp[8];
__device__ unsigned int g_prep;
__device__ unsigned int g_ctr;
__device__ unsigned int g_fin;

// ---------------- helpers ----------------
__device__ __forceinline__ uint32_t smem_u32(const void* p) {
    uint32_t a;
    asm("{ .reg .u64 t; cvta.to.shared.u64 t, %1; cvt.u32.u64 %0, t; }" : "=r"(a) : "l"(p));
    return a;
}
__device__ __forceinline__ uint32_t sw128(uint32_t off) {
    return off ^ ((off >> 3) & 0x70);
}
__device__ __forceinline__ void ldsm_x4(uint32_t* r, uint32_t addr) {
    asm volatile("ldmatrix.sync.aligned.m8n8.x4.shared.b16 {%0,%1,%2,%3}, [%4];"
                 : "=r"(r[0]), "=r"(r[1]), "=r"(r[2]), "=r"(r[3]) : "r"(addr));
}
__device__ __forceinline__ void mma_f16(float* c, const uint32_t* a, uint32_t b0, uint32_t b1) {
    asm volatile("mma.sync.aligned.m16n8k16.row.col.f32.f16.f16.f32 "
                 "{%0,%1,%2,%3}, {%4,%5,%6,%7}, {%8,%9}, {%0,%1,%2,%3};"
                 : "+f"(c[0]), "+f"(c[1]), "+f"(c[2]), "+f"(c[3])
                 : "r"(a[0]), "r"(a[1]), "r"(a[2]), "r"(a[3]), "r"(b0), "r"(b1));
}
__device__ __forceinline__ void cp16(uint32_t saddr, const void* gptr) {
    asm volatile("cp.async.cg.shared.global [%0], [%1], 16;"
                 :: "r"(saddr), "l"(__cvta_generic_to_global(gptr)));
}
#define CP_COMMIT() asm volatile("cp.async.commit_group;" ::: "memory")
#define CP_WAIT(n)  asm volatile("cp.async.wait_group %0;" :: "n"(n) : "memory")
__device__ __forceinline__ unsigned int ld_cg_u32(const unsigned int* p) {
    unsigned int v;
    asm volatile("ld.global.cg.u32 %0, [%1];" : "=r"(v) : "l"(p));
    return v;
}

// ---------------- single fused kernel, 256 threads, 2-stage (R14) ----------------
#define OFF_A 0
#define OFF_B 16384
#define STAGE_BYTES 32768
#define SMEM_BYTES  (2 * STAGE_BYTES)

__global__ void __launch_bounds__(256, 2) fused_kernel(const float* __restrict__ feats,
                                                       const int* __restrict__ index,
                                                       const float* __restrict__ u,
                                                       float* __restrict__ out) {
    extern __shared__ char smem[];
    const uint32_t sb = smem_u32(smem);
    const int tid  = threadIdx.x;
    const int lane = tid & 31;
    const int wid  = tid >> 5;
    const int wm   = wid & 1;       // M half (64 rows)
    const int wn   = wid >> 1;      // N quarter (32 cols)

    // ---------------- phase 0: prep (producer CTAs bid < 256, all wave-1) ----------------
    if (blockIdx.x < NPREP) {
#pragma unroll
        for (int it = 0; it < 4; it++) {
            int e = (blockIdx.x * 1024 + it * 256 + tid) * 4;
            int n = e >> 8;
            int d = e & 255;
            int v = n >> 11;
            int b = n & 2047;
            float4 f = *(const float4*)&feats[((b << 1) | v) * D_ + d];
            uint2 hp;
            hp.x = ((uint32_t)__half_as_ushort(__float2half(f.y)) << 16) | __half_as_ushort(__float2half(f.x));
            hp.y = ((uint32_t)__half_as_ushort(__float2half(f.w)) << 16) | __half_as_ushort(__float2half(f.z));
            *(uint2*)&g_Fh[e] = hp;
        }
        __threadfence();
        __syncthreads();
        if (tid == 0) atomicAdd(&g_prep, 1u);
    }
    if (tid == 0) {
        while (ld_cg_u32(&g_prep) < (unsigned)NPREP) { __nanosleep(60); }
    }
    __syncthreads();
    __threadfence();

    // decode upper-triangular tile (bi, bj), bi <= bj
    int bi = 0, rem = blockIdx.x;
    while (rem >= (NB_ - bi)) { rem -= (NB_ - bi); bi++; }
    const int bj = bi + rem;
    const int row0 = bi * 128;
    const int col0 = bj * 128;

    // staging coords
    int sr[4], sc[4];
    uint32_t ssw[4];
#pragma unroll
    for (int it = 0; it < 4; it++) {
        int q = tid + it * 256;
        sr[it] = q >> 3;
        sc[it] = q & 7;
        ssw[it] = sw128((uint32_t)(sr[it] * 128 + sc[it] * 16));
    }

    // prefetch chunk 0 into stage 0
#pragma unroll
    for (int it = 0; it < 4; it++) {
        cp16(sb + OFF_A + ssw[it], &g_Fh[(row0 + sr[it]) * D_ + sc[it] * 8]);
        cp16(sb + OFF_B + ssw[it], &g_Fh[(col0 + sr[it]) * D_ + sc[it] * 8]);
    }
    CP_COMMIT();

    float acc[4][4][4];
#pragma unroll
    for (int mi = 0; mi < 4; mi++)
#pragma unroll
        for (int nj = 0; nj < 4; nj++)
#pragma unroll
            for (int c = 0; c < 4; c++) acc[mi][nj][c] = 0.0f;

    const int arow  = wm * 64 + (lane & 7) + ((lane >> 3) & 1) * 8;
    const int akc0  = (lane >> 4) * 8;
    const int brow  = wn * 32 + (lane & 7) + (lane >> 4) * 8;
    const int bkc0  = ((lane >> 3) & 1) * 8;

    for (int kc = 0; kc < 4; kc++) {
        if (kc < 3) {
            uint32_t nb = sb + ((kc + 1) & 1) * STAGE_BYTES;
#pragma unroll
            for (int it = 0; it < 4; it++) {
                cp16(nb + OFF_A + ssw[it], &g_Fh[(row0 + sr[it]) * D_ + (kc + 1) * 64 + sc[it] * 8]);
                cp16(nb + OFF_B + ssw[it], &g_Fh[(col0 + sr[it]) * D_ + (kc + 1) * 64 + sc[it] * 8]);
            }
            CP_COMMIT();
            CP_WAIT(1);
        } else {
            CP_WAIT(0);
        }
        __syncthreads();

        const uint32_t cb = sb + (kc & 1) * STAGE_BYTES;

        // B-fragment ping-pong across ks: b(ks+1) issued before the MMAs of ks.
        uint32_t bq[2][2][4];
#pragma unroll
        for (int b2 = 0; b2 < 2; b2++)
            ldsm_x4(bq[0][b2], cb + OFF_B + sw128((uint32_t)((brow + b2 * 16) * 128 + bkc0 * 2)));
#pragma unroll
        for (int ks = 0; ks < 4; ks++) {
            const int cur = ks & 1;
            const int nxt = cur ^ 1;
            const int akc = ks * 16 + akc0;
            uint32_t a[4][4];
#pragma unroll
            for (int mi = 0; mi < 4; mi++)
                ldsm_x4(a[mi], cb + OFF_A + sw128((uint32_t)((arow + mi * 16) * 128 + akc * 2)));
            if (ks < 3) {
                const int bkcn = (ks + 1) * 16 + bkc0;
#pragma unroll
                for (int b2 = 0; b2 < 2; b2++)
                    ldsm_x4(bq[nxt][b2], cb + OFF_B + sw128((uint32_t)((brow + b2 * 16) * 128 + bkcn * 2)));
            }
#pragma unroll
            for (int mi = 0; mi < 4; mi++)
#pragma unroll
                for (int nj = 0; nj < 4; nj++) {
                    uint32_t b0 = (nj & 1) ? bq[cur][nj >> 1][2] : bq[cur][nj >> 1][0];
                    uint32_t b1 = (nj & 1) ? bq[cur][nj >> 1][3] : bq[cur][nj >> 1][1];
                    mma_f16(acc[mi][nj], a[mi], b0, b1);
                }
        }
        __syncthreads();
    }

    // ---------------- epilogue: fused row+col stats, fixed-m0 exp ----------------
    float* redm = (float*)smem;          // [128][4] row partials
    float* rede = redm + 512;
    float* redg = rede + 512;
    float* colm_s = redg + 512;          // [128][2] col partials
    float* cole_s = colm_s + 256;
    float* colg_s = cole_s + 256;
    const float invT = 1.0f / TEMP_F;
    const bool offd = (bi != bj);

    float colE[8], colG[8], colM[8];
#pragma unroll
    for (int k = 0; k < 8; k++) { colE[k] = 0.0f; colG[k] = 0.0f; colM[k] = -1e30f; }

#pragma unroll
    for (int mi = 0; mi < 4; mi++) {
#pragma unroll
        for (int h = 0; h < 2; h++) {
            int lr = wm * 64 + mi * 16 + h * 8 + (lane >> 2);
            int gi = row0 + lr;
            int posj = (gi + B_) & (NTOT - 1);
            float rE = 0.0f, rG = 0.0f, rM = -1e30f;
#pragma unroll
            for (int nj = 0; nj < 4; nj++) {
#pragma unroll
                for (int c = 0; c < 2; c++) {
                    const int k = nj * 2 + c;
                    float raw = acc[mi][nj][h * 2 + c];
                    int gj = col0 + wn * 32 + nj * 8 + (lane & 3) * 2 + c;
                    rM = fmaxf(rM, raw);
                    if (offd) colM[k] = fmaxf(colM[k], raw);
                    if (gj == posj) {
                        g_SP[gi] = raw;                  // row gi's positive
                        g_SP[gj] = raw;                  // row gj's positive (symmetric)
                    } else {
                        float e = __expf((raw - 1.0f) * invT);
                        rE += e;
                        rG = fmaf(e, raw, rG);
                        if (offd) {
                            colE[k] += e;
                            colG[k] = fmaf(e, raw, colG[k]);
                        }
                    }
                }
            }
            rM = fmaxf(rM, __shfl_xor_sync(0xffffffffu, rM, 1));
            rM = fmaxf(rM, __shfl_xor_sync(0xffffffffu, rM, 2));
            rE += __shfl_xor_sync(0xffffffffu, rE, 1);
            rE += __shfl_xor_sync(0xffffffffu, rE, 2);
            rG += __shfl_xor_sync(0xffffffffu, rG, 1);
            rG += __shfl_xor_sync(0xffffffffu, rG, 2);
            if ((lane & 3) == 0) {
                redm[lr * 4 + wn] = rM;
                rede[lr * 4 + wn] = rE;
                redg[lr * 4 + wn] = rG;
            }
        }
    }

    if (offd) {
#pragma unroll
        for (int k = 0; k < 8; k++) {
            int cid = wn * 32 + (k >> 1) * 8 + (lane & 3) * 2 + (k & 1);
            float m = colM[k], E = colE[k], G = colG[k];
            m = fmaxf(m, __shfl_xor_sync(0xffffffffu, m, 4));
            m = fmaxf(m, __shfl_xor_sync(0xffffffffu, m, 8));
            m = fmaxf(m, __shfl_xor_sync(0xffffffffu, m, 16));
            E += __shfl_xor_sync(0xffffffffu, E, 4);
            E += __shfl_xor_sync(0xffffffffu, E, 8);
            E += __shfl_xor_sync(0xffffffffu, E, 16);
            G += __shfl_xor_sync(0xffffffffu, G, 4);
            G += __shfl_xor_sync(0xffffffffu, G, 8);
            G += __shfl_xor_sync(0xffffffffu, G, 16);
            if ((lane >> 2) == 0) {
                colm_s[cid * 2 + wm] = m;
                cole_s[cid * 2 + wm] = E;
                colg_s[cid * 2 + wm] = G;
            }
        }
    }

    __syncthreads();
    if (tid < 128) {
        float mm = redm[tid * 4], ee = rede[tid * 4], gg = redg[tid * 4];
#pragma unroll
        for (int t = 1; t < 4; t++) {
            mm = fmaxf(mm, redm[tid * 4 + t]);
            ee += rede[tid * 4 + t];
            gg += redg[tid * 4 + t];
        }
        g_Mp[bj * NTOT + row0 + tid] = mm;
        g_Ep[bj * NTOT + row0 + tid] = ee;
        g_Gp[bj * NTOT + row0 + tid] = gg;
    } else if (offd && tid < 256) {
        int cid = tid - 128;
        float mm = fmaxf(colm_s[cid * 2], colm_s[cid * 2 + 1]);
        float ee = cole_s[cid * 2] + cole_s[cid * 2 + 1];
        float gg = colg_s[cid * 2] + colg_s[cid * 2 + 1];
        g_Mp[bi * NTOT + col0 + cid] = mm;
        g_Ep[bi * NTOT + col0 + cid] = ee;
        g_Gp[bi * NTOT + col0 + cid] = gg;
    }

    // ---------------- done-ticket + fused combine (CTAs 0..7) ----------------
    __threadfence();
    __syncthreads();
    if (tid == 0) atomicAdd(&g_ctr, 1u);

    if (blockIdx.x < 8) {
        if (tid == 0) {
            while (ld_cg_u32(&g_ctr) < (unsigned)NTILES) { __nanosleep(100); }
        }
        __syncthreads();
        __threadfence();

        __shared__ float red[8];
        int b = blockIdx.x * 256 + tid;            // [0, 2048)
        float m1 = -1e30f, E1 = 0.0f, G1 = 0.0f;   // row b
        float m2 = -1e30f, E2 = 0.0f, G2 = 0.0f;   // row b+2048
#pragma unroll
        for (int s = 0; s < NB_; s++) {
            m1 = fmaxf(m1, g_Mp[s * NTOT + b]);
            E1 += g_Ep[s * NTOT + b];
            G1 += g_Gp[s * NTOT + b];
            m2 = fmaxf(m2, g_Mp[s * NTOT + B_ + b]);
            E2 += g_Ep[s * NTOT + B_ + b];
            G2 += g_Gp[s * NTOT + B_ + b];
        }
        const float invT2 = 1.0f / TEMP_F;
        float em1 = __expf((1.0f - m1) * invT2);
        float em2 = __expf((1.0f - m2) * invT2);
        float u_new = (1.0f - GAMMA_F) * u[index[b]] + GAMMA_F * em1 * E1;
        float t1 = em1 * invT2 * (G1 - m1 * E1) / u_new;
        float t2 = em2 * invT2 * (G2 - m2 * E2) / u_new;
        const float k = -(TEMP_F / BASET_F) * (1.0f / (float)NTOT);
        float val = k * ((invT2 * (g_SP[b]      - m1) - t1) +
                         (invT2 * (g_SP[B_ + b] - m2) - t2));
#pragma unroll
        for (int o = 16; o; o >>= 1) val += __shfl_down_sync(0xffffffffu, val, o);
        if ((tid & 31) == 0) red[tid >> 5] = val;
        __syncthreads();
        if (tid < 8) {
            float v = red[tid];
#pragma unroll
            for (int o = 4; o; o >>= 1) v += __shfl_down_sync(0xffu, v, o);
            if (tid == 0) {
                g_Lp[blockIdx.x] = v;
                __threadfence();
                unsigned int t = atomicAdd(&g_fin, 1u);
                if (t == 7u) {
                    float s = 0.0f;
#pragma unroll
                    for (int i = 0; i < 8; i++) s += g_Lp[i];
                    out[0] = s;
                    g_prep = 0;
                    g_ctr  = 0;
                    g_fin  = 0;
                }
            }
        }
    }
}

// ---------------- launch ----------------
extern "C" void kernel_launch(void* const* d_in, const int* in_sizes, int n_in,
                              void* d_out, int out_size) {
    const int*   d_index = nullptr;
    const float* d_feats = nullptr;
    const float* d_u     = nullptr;
    for (int i = 0; i < n_in; i++) {
        if (in_sizes[i] == B_)                 d_index = (const int*)d_in[i];
        else if (in_sizes[i] == B_ * V_ * D_)  d_feats = (const float*)d_in[i];
        else                                   d_u     = (const float*)d_in[i];
    }
    float* out = (float*)d_out;

    cudaFuncSetAttribute(fused_kernel,
                         cudaFuncAttributeMaxDynamicSharedMemorySize, SMEM_BYTES);

    fused_kernel<<<NTILES, 256, SMEM_BYTES>>>(d_feats, d_index, d_u, out);
}

// round 17
// speedup vs baseline: 1.0427x; 1.0260x over previous
#include <cuda_runtime.h>
#include <cuda_fp16.h>
#include <stdint.h>

// ---------------- problem constants ----------------
#define B_    2048
#define V_    2
#define D_    256
#define NTOT  4096
#define NB_   32              // 128-wide blocks per dimension
#define NTILES 528            // NB*(NB+1)/2 upper-triangular tiles
#define NPREP  256            // producer CTAs for the prep phase
#define GAMMA_F   0.9f
#define TEMP_F    0.07f
#define BASET_F   0.07f

// ---------------- device scratch ----------------
// Row max is analytically 1.0 (unit-normalized features; diagonal dominates),
// so only E = sum exp((raw-1)/T) and G = sum e*raw are tracked.
__device__ __half g_Fh[NTOT * D_];
__device__ float g_Ep[NB_ * NTOT];
__device__ float g_Gp[NB_ * NTOT];
__device__ float g_SP[NTOT];         // raw positive logit
__device__ float g_Lp[8];
__device__ unsigned int g_prep;
__device__ unsigned int g_ctr;
__device__ unsigned int g_fin;

// ---------------- helpers ----------------
__device__ __forceinline__ uint32_t smem_u32(const void* p) {
    uint32_t a;
    asm("{ .reg .u64 t; cvta.to.shared.u64 t, %1; cvt.u32.u64 %0, t; }" : "=r"(a) : "l"(p));
    return a;
}
__device__ __forceinline__ uint32_t sw128(uint32_t off) {
    return off ^ ((off >> 3) & 0x70);
}
__device__ __forceinline__ void ldsm_x4(uint32_t* r, uint32_t addr) {
    asm volatile("ldmatrix.sync.aligned.m8n8.x4.shared.b16 {%0,%1,%2,%3}, [%4];"
                 : "=r"(r[0]), "=r"(r[1]), "=r"(r[2]), "=r"(r[3]) : "r"(addr));
}
__device__ __forceinline__ void mma_f16(float* c, const uint32_t* a, uint32_t b0, uint32_t b1) {
    asm volatile("mma.sync.aligned.m16n8k16.row.col.f32.f16.f16.f32 "
                 "{%0,%1,%2,%3}, {%4,%5,%6,%7}, {%8,%9}, {%0,%1,%2,%3};"
                 : "+f"(c[0]), "+f"(c[1]), "+f"(c[2]), "+f"(c[3])
                 : "r"(a[0]), "r"(a[1]), "r"(a[2]), "r"(a[3]), "r"(b0), "r"(b1));
}
__device__ __forceinline__ void cp16(uint32_t saddr, const void* gptr) {
    asm volatile("cp.async.cg.shared.global [%0], [%1], 16;"
                 :: "r"(saddr), "l"(__cvta_generic_to_global(gptr)));
}
#define CP_COMMIT() asm volatile("cp.async.commit_group;" ::: "memory")
#define CP_WAIT(n)  asm volatile("cp.async.wait_group %0;" :: "n"(n) : "memory")
__device__ __forceinline__ unsigned int ld_cg_u32(const unsigned int* p) {
    unsigned int v;
    asm volatile("ld.global.cg.u32 %0, [%1];" : "=r"(v) : "l"(p));
    return v;
}

// ---------------- single fused kernel, 256 threads, 2-stage ----------------
#define OFF_A 0
#define OFF_B 16384
#define STAGE_BYTES 32768
#define SMEM_BYTES  (2 * STAGE_BYTES)

__global__ void __launch_bounds__(256, 2) fused_kernel(const float* __restrict__ feats,
                                                       const int* __restrict__ index,
                                                       const float* __restrict__ u,
                                                       float* __restrict__ out) {
    extern __shared__ char smem[];
    const uint32_t sb = smem_u32(smem);
    const int tid  = threadIdx.x;
    const int lane = tid & 31;
    const int wid  = tid >> 5;
    const int wm   = wid & 1;       // M half (64 rows)
    const int wn   = wid >> 1;      // N quarter (32 cols)

    // ---------------- phase 0: prep (producer CTAs bid < 256, all wave-1) ----------------
    if (blockIdx.x < NPREP) {
#pragma unroll
        for (int it = 0; it < 4; it++) {
            int e = (blockIdx.x * 1024 + it * 256 + tid) * 4;
            int n = e >> 8;
            int d = e & 255;
            int v = n >> 11;
            int b = n & 2047;
            float4 f = *(const float4*)&feats[((b << 1) | v) * D_ + d];
            uint2 hp;
            hp.x = ((uint32_t)__half_as_ushort(__float2half(f.y)) << 16) | __half_as_ushort(__float2half(f.x));
            hp.y = ((uint32_t)__half_as_ushort(__float2half(f.w)) << 16) | __half_as_ushort(__float2half(f.z));
            *(uint2*)&g_Fh[e] = hp;
        }
        __threadfence();
        __syncthreads();
        if (tid == 0) atomicAdd(&g_prep, 1u);
    }
    if (tid == 0) {
        while (ld_cg_u32(&g_prep) < (unsigned)NPREP) { __nanosleep(60); }
    }
    __syncthreads();
    __threadfence();

    // decode upper-triangular tile (bi, bj), bi <= bj
    int bi = 0, rem = blockIdx.x;
    while (rem >= (NB_ - bi)) { rem -= (NB_ - bi); bi++; }
    const int bj = bi + rem;
    const int row0 = bi * 128;
    const int col0 = bj * 128;

    // staging coords
    int sr[4], sc[4];
    uint32_t ssw[4];
#pragma unroll
    for (int it = 0; it < 4; it++) {
        int q = tid + it * 256;
        sr[it] = q >> 3;
        sc[it] = q & 7;
        ssw[it] = sw128((uint32_t)(sr[it] * 128 + sc[it] * 16));
    }

    // prefetch chunk 0 into stage 0
#pragma unroll
    for (int it = 0; it < 4; it++) {
        cp16(sb + OFF_A + ssw[it], &g_Fh[(row0 + sr[it]) * D_ + sc[it] * 8]);
        cp16(sb + OFF_B + ssw[it], &g_Fh[(col0 + sr[it]) * D_ + sc[it] * 8]);
    }
    CP_COMMIT();

    float acc[4][4][4];
#pragma unroll
    for (int mi = 0; mi < 4; mi++)
#pragma unroll
        for (int nj = 0; nj < 4; nj++)
#pragma unroll
            for (int c = 0; c < 4; c++) acc[mi][nj][c] = 0.0f;

    const int arow  = wm * 64 + (lane & 7) + ((lane >> 3) & 1) * 8;
    const int akc0  = (lane >> 4) * 8;
    const int brow  = wn * 32 + (lane & 7) + (lane >> 4) * 8;
    const int bkc0  = ((lane >> 3) & 1) * 8;

    for (int kc = 0; kc < 4; kc++) {
        if (kc < 3) {
            uint32_t nb = sb + ((kc + 1) & 1) * STAGE_BYTES;
#pragma unroll
            for (int it = 0; it < 4; it++) {
                cp16(nb + OFF_A + ssw[it], &g_Fh[(row0 + sr[it]) * D_ + (kc + 1) * 64 + sc[it] * 8]);
                cp16(nb + OFF_B + ssw[it], &g_Fh[(col0 + sr[it]) * D_ + (kc + 1) * 64 + sc[it] * 8]);
            }
            CP_COMMIT();
            CP_WAIT(1);
        } else {
            CP_WAIT(0);
        }
        __syncthreads();

        const uint32_t cb = sb + (kc & 1) * STAGE_BYTES;

        // B-fragment ping-pong across ks
        uint32_t bq[2][2][4];
#pragma unroll
        for (int b2 = 0; b2 < 2; b2++)
            ldsm_x4(bq[0][b2], cb + OFF_B + sw128((uint32_t)((brow + b2 * 16) * 128 + bkc0 * 2)));
#pragma unroll
        for (int ks = 0; ks < 4; ks++) {
            const int cur = ks & 1;
            const int nxt = cur ^ 1;
            const int akc = ks * 16 + akc0;
            uint32_t a[4][4];
#pragma unroll
            for (int mi = 0; mi < 4; mi++)
                ldsm_x4(a[mi], cb + OFF_A + sw128((uint32_t)((arow + mi * 16) * 128 + akc * 2)));
            if (ks < 3) {
                const int bkcn = (ks + 1) * 16 + bkc0;
#pragma unroll
                for (int b2 = 0; b2 < 2; b2++)
                    ldsm_x4(bq[nxt][b2], cb + OFF_B + sw128((uint32_t)((brow + b2 * 16) * 128 + bkcn * 2)));
            }
#pragma unroll
            for (int mi = 0; mi < 4; mi++)
#pragma unroll
                for (int nj = 0; nj < 4; nj++) {
                    uint32_t b0 = (nj & 1) ? bq[cur][nj >> 1][2] : bq[cur][nj >> 1][0];
                    uint32_t b1 = (nj & 1) ? bq[cur][nj >> 1][3] : bq[cur][nj >> 1][1];
                    mma_f16(acc[mi][nj], a[mi], b0, b1);
                }
        }
        __syncthreads();
    }

    // ---------------- epilogue: fused row+col E/G stats (m = 1.0 analytic) ----------------
    float* rede = (float*)smem;          // [128][4] row partials
    float* redg = rede + 512;
    float* cole_s = redg + 512;          // [128][2] col partials
    float* colg_s = cole_s + 256;
    const float invT = 1.0f / TEMP_F;
    const bool offd = (bi != bj);

    float colE[8], colG[8];
#pragma unroll
    for (int k = 0; k < 8; k++) { colE[k] = 0.0f; colG[k] = 0.0f; }

#pragma unroll
    for (int mi = 0; mi < 4; mi++) {
#pragma unroll
        for (int h = 0; h < 2; h++) {
            int lr = wm * 64 + mi * 16 + h * 8 + (lane >> 2);
            int gi = row0 + lr;
            int posj = (gi + B_) & (NTOT - 1);
            float rE = 0.0f, rG = 0.0f;
#pragma unroll
            for (int nj = 0; nj < 4; nj++) {
#pragma unroll
                for (int c = 0; c < 2; c++) {
                    const int k = nj * 2 + c;
                    float raw = acc[mi][nj][h * 2 + c];
                    int gj = col0 + wn * 32 + nj * 8 + (lane & 3) * 2 + c;
                    if (gj == posj) {
                        g_SP[gi] = raw;                  // row gi's positive
                        g_SP[gj] = raw;                  // row gj's positive (symmetric)
                    } else {
                        float e = __expf((raw - 1.0f) * invT);
                        rE += e;
                        rG = fmaf(e, raw, rG);
                        if (offd) {
                            colE[k] += e;
                            colG[k] = fmaf(e, raw, colG[k]);
                        }
                    }
                }
            }
            rE += __shfl_xor_sync(0xffffffffu, rE, 1);
            rE += __shfl_xor_sync(0xffffffffu, rE, 2);
            rG += __shfl_xor_sync(0xffffffffu, rG, 1);
            rG += __shfl_xor_sync(0xffffffffu, rG, 2);
            if ((lane & 3) == 0) {
                rede[lr * 4 + wn] = rE;
                redg[lr * 4 + wn] = rG;
            }
        }
    }

    if (offd) {
#pragma unroll
        for (int k = 0; k < 8; k++) {
            int cid = wn * 32 + (k >> 1) * 8 + (lane & 3) * 2 + (k & 1);
            float E = colE[k], G = colG[k];
            E += __shfl_xor_sync(0xffffffffu, E, 4);
            E += __shfl_xor_sync(0xffffffffu, E, 8);
            E += __shfl_xor_sync(0xffffffffu, E, 16);
            G += __shfl_xor_sync(0xffffffffu, G, 4);
            G += __shfl_xor_sync(0xffffffffu, G, 8);
            G += __shfl_xor_sync(0xffffffffu, G, 16);
            if ((lane >> 2) == 0) {
                cole_s[cid * 2 + wm] = E;
                colg_s[cid * 2 + wm] = G;
            }
        }
    }

    __syncthreads();
    if (tid < 128) {
        float ee = rede[tid * 4], gg = redg[tid * 4];
#pragma unroll
        for (int t = 1; t < 4; t++) {
            ee += rede[tid * 4 + t];
            gg += redg[tid * 4 + t];
        }
        g_Ep[bj * NTOT + row0 + tid] = ee;
        g_Gp[bj * NTOT + row0 + tid] = gg;
    } else if (offd && tid < 256) {
        int cid = tid - 128;
        g_Ep[bi * NTOT + col0 + cid] = cole_s[cid * 2] + cole_s[cid * 2 + 1];
        g_Gp[bi * NTOT + col0 + cid] = colg_s[cid * 2] + colg_s[cid * 2 + 1];
    }

    // ---------------- done-ticket + fused combine (CTAs 0..7) ----------------
    __threadfence();
    __syncthreads();
    if (tid == 0) atomicAdd(&g_ctr, 1u);

    if (blockIdx.x < 8) {
        if (tid == 0) {
            while (ld_cg_u32(&g_ctr) < (unsigned)NTILES) { __nanosleep(100); }
        }
        __syncthreads();
        __threadfence();

        __shared__ float red[8];
        int b = blockIdx.x * 256 + tid;            // [0, 2048)
        float E1 = 0.0f, G1 = 0.0f;                // row b
        float E2 = 0.0f, G2 = 0.0f;                // row b+2048
#pragma unroll
        for (int s = 0; s < NB_; s++) {
            E1 += g_Ep[s * NTOT + b];
            G1 += g_Gp[s * NTOT + b];
            E2 += g_Ep[s * NTOT + B_ + b];
            G2 += g_Gp[s * NTOT + B_ + b];
        }
        const float invT2 = 1.0f / TEMP_F;
        // logits = (raw - 1)/T; A (neg exp sum) = E; W (sum p*logits numer) = (G - E)/T
        float u_new = (1.0f - GAMMA_F) * u[index[b]] + GAMMA_F * E1;
        float t1 = invT2 * (G1 - E1) / u_new;
        float t2 = invT2 * (G2 - E2) / u_new;
        const float k = -(TEMP_F / BASET_F) * (1.0f / (float)NTOT);
        float val = k * ((invT2 * (g_SP[b]      - 1.0f) - t1) +
                         (invT2 * (g_SP[B_ + b] - 1.0f) - t2));
#pragma unroll
        for (int o = 16; o; o >>= 1) val += __shfl_down_sync(0xffffffffu, val, o);
        if ((tid & 31) == 0) red[tid >> 5] = val;
        __syncthreads();
        if (tid < 8) {
            float v = red[tid];
#pragma unroll
            for (int o = 4; o; o >>= 1) v += __shfl_down_sync(0xffu, v, o);
            if (tid == 0) {
                g_Lp[blockIdx.x] = v;
                __threadfence();
                unsigned int t = atomicAdd(&g_fin, 1u);
                if (t == 7u) {
                    float s = 0.0f;
#pragma unroll
                    for (int i = 0; i < 8; i++) s += g_Lp[i];
                    out[0] = s;
                    g_prep = 0;
                    g_ctr  = 0;
                    g_fin  = 0;
                }
            }
        }
    }
}

// ---------------- launch ----------------
extern "C" void kernel_launch(void* const* d_in, const int* in_sizes, int n_in,
                              void* d_out, int out_size) {
    const int*   d_index = nullptr;
    const float* d_feats = nullptr;
    const float* d_u     = nullptr;
    for (int i = 0; i < n_in; i++) {
        if (in_sizes[i] == B_)                 d_index = (const int*)d_in[i];
        else if (in_sizes[i] == B_ * V_ * D_)  d_feats = (const float*)d_in[i];
        else                                   d_u     = (const float*)d_in[i];
    }
    float* out = (float*)d_out;

    cudaFuncSetAttribute(fused_kernel,
                         cudaFuncAttributeMaxDynamicSharedMemorySize, SMEM_BYTES);

    fused_kernel<<<NTILES, 256, SMEM_BYTES>>>(d_feats, d_index, d_u, out);
}